// round 12
// baseline (speedup 1.0000x reference)
#include <cuda_runtime.h>
#include <cuda_fp16.h>
#include <cstdint>

// ---------------- problem constants ----------------
constexpr int Bq = 4096;
constexpr int Eq = 512;   // K
constexpr int Tq = 32;
constexpr int Hq = 256;
constexpr int ITq = 5;
#define EPSq 1e-6f

// ---------------- fragment-ready scratch ----------------
// A frags: [mtile32 128][ks 32][mfrag 2][lane 32][8 halves]       = 4 MB
// B frags: [tok 32][ks 32][warp 8][fpair 4][lane 32][8 halves]    = 16 MB
__device__ __align__(256) __half g_xa[(size_t)128 * 32 * 2 * 32 * 8];
__device__ __align__(256) __half g_xb[(size_t)32 * 32 * 8 * 4 * 32 * 8];

// fp16-accumulating MMA: D,C fp16 (2 regs)
__device__ __forceinline__ void mma16816_f16(uint32_t* d, const uint32_t* a,
                                             const uint32_t* b) {
    asm volatile(
        "mma.sync.aligned.m16n8k16.row.col.f16.f16.f16.f16 "
        "{%0,%1},{%2,%3,%4,%5},{%6,%7},{%0,%1};"
        : "+r"(d[0]), "+r"(d[1])
        : "r"(a[0]), "r"(a[1]), "r"(a[2]), "r"(a[3]), "r"(b[0]), "r"(b[1]));
}

// ---------------- kernel 1: fused conversions ----------------
__global__ __launch_bounds__(256)
void convert_kernel(const float* __restrict__ x,
                    const float* __restrict__ w_in,
                    const float* __restrict__ w_val) {
    __shared__ float tile[32][33];
    if (blockIdx.x < 1024) {
        const int idx   = blockIdx.x * 256 + threadIdx.x;
        const int lane  = idx & 31;
        const int mfrag = (idx >> 5) & 1;
        const int ks    = (idx >> 6) & 31;
        const int mtile = idx >> 11;
        const int r0 = mtile * 32 + mfrag * 16 + (lane >> 2);
        const int c0 = ks * 16 + 2 * (lane & 3);
        const float* xr0 = x + (size_t)r0 * Eq;
        const float* xr1 = xr0 + 8 * Eq;
        __half h[8];
        h[0] = __float2half_rn(xr0[c0]);     h[1] = __float2half_rn(xr0[c0 + 1]);
        h[2] = __float2half_rn(xr1[c0]);     h[3] = __float2half_rn(xr1[c0 + 1]);
        h[4] = __float2half_rn(xr0[c0 + 8]); h[5] = __float2half_rn(xr0[c0 + 9]);
        h[6] = __float2half_rn(xr1[c0 + 8]); h[7] = __float2half_rn(xr1[c0 + 9]);
        reinterpret_cast<uint4*>(g_xa)[idx] = *reinterpret_cast<uint4*>(h);
        return;
    }
    const int bz = blockIdx.x - 1024;       // 0..8191
    const int e0 = (bz & 15) * 32;
    const int h0 = ((bz >> 4) & 7) * 32;
    const int z  = bz >> 7;
    const int m  = z >> 5;
    const int t  = z & 31;
    const float* src = (m ? w_val : w_in) + (size_t)t * Eq * Hq;
    const int tx = threadIdx.x & 31;
    const int ty = threadIdx.x >> 5;
    #pragma unroll
    for (int r = ty; r < 32; r += 8)
        tile[r][tx] = src[(size_t)(e0 + r) * Hq + h0 + tx];
    __syncthreads();
    const int lane = threadIdx.x & 31;
    const int f    = (threadIdx.x >> 5) & 3;
    const int ksl  = threadIdx.x >> 7;            // 0/1
    const int ks   = (e0 >> 4) + ksl;
    const int k0   = ksl * 16 + 2 * (lane & 3);
    const int hc   = f * 8 + (lane >> 2);
    const int wp   = h0 >> 5;
    const int fi   = f + m * 4;                   // 0..7
    __half hv[4];
    hv[0] = __float2half_rn(tile[k0][hc]);
    hv[1] = __float2half_rn(tile[k0 + 1][hc]);
    hv[2] = __float2half_rn(tile[k0 + 8][hc]);
    hv[3] = __float2half_rn(tile[k0 + 9][hc]);
    const size_t di = (((((size_t)t * 32 + ks) * 8 + wp) * 4 + (fi >> 1)) * 32
                      + lane) * 2 + (fi & 1);
    reinterpret_cast<uint2*>(g_xb)[di] = *reinterpret_cast<uint2*>(hv);
}

// ---------------- kernel 2: fp16-acc GEMM + fused epilogue ----------------
__global__ __launch_bounds__(256, 1)
void gemm_fused_kernel(const float* __restrict__ alphas,
                       const float* __restrict__ scales,
                       const float* __restrict__ gamma,
                       const float* __restrict__ beta,
                       float* __restrict__ out)
{
    __shared__ float red[2][8][32];

    const int tid  = threadIdx.x;
    const int wid  = tid >> 5;
    const int lane = tid & 31;
    const int mtile = blockIdx.x;   // 0..127
    const int tok   = blockIdx.y;   // 0..31
    const int b0    = mtile * 32;

    const uint4* pa = reinterpret_cast<const uint4*>(g_xa)
                    + ((size_t)mtile * 32) * 2 * 32 + lane;
    const uint4* pb = reinterpret_cast<const uint4*>(g_xb)
                    + (((size_t)tok * 32) * 8 + wid) * 4 * 32 + lane;

    float acc[2][8][4];          // fp32 master accumulators
    uint32_t hacc[2][8][2];      // fp16 span accumulators
    #pragma unroll
    for (int i = 0; i < 2; i++)
        #pragma unroll
        for (int j = 0; j < 8; j++) {
            #pragma unroll
            for (int k = 0; k < 4; k++) acc[i][j][k] = 0.0f;
            hacc[i][j][0] = 0u; hacc[i][j][1] = 0u;
        }

    uint4 a0[2], a1[2];
    uint4 bb0[4], bb1[4];

    #define LOAD_A(ks, A) do {                                   \
        A[0] = pa[(size_t)(ks) * 64];                            \
        A[1] = pa[(size_t)(ks) * 64 + 32];                       \
    } while (0)
    #define LOAD_B(ks, BB) do {                                  \
        _Pragma("unroll")                                        \
        for (int j = 0; j < 4; j++)                              \
            BB[j] = pb[(size_t)(ks) * 1024 + j * 32];            \
    } while (0)
    #define DO_MMA(A, BB) do {                                   \
        _Pragma("unroll")                                        \
        for (int mf = 0; mf < 2; mf++)                           \
            _Pragma("unroll")                                    \
            for (int f = 0; f < 8; f++)                          \
                mma16816_f16(hacc[mf][f],                        \
                         reinterpret_cast<const uint32_t*>(&A[mf]), \
                         reinterpret_cast<const uint32_t*>(&BB[f >> 1]) + (f & 1) * 2); \
    } while (0)
    #define PROMOTE() do {                                       \
        _Pragma("unroll")                                        \
        for (int mf = 0; mf < 2; mf++)                           \
            _Pragma("unroll")                                    \
            for (int f = 0; f < 8; f++) {                        \
                float2 f0 = __half22float2(                      \
                    *reinterpret_cast<__half2*>(&hacc[mf][f][0]));\
                float2 f1 = __half22float2(                      \
                    *reinterpret_cast<__half2*>(&hacc[mf][f][1]));\
                acc[mf][f][0] += f0.x; acc[mf][f][1] += f0.y;    \
                acc[mf][f][2] += f1.x; acc[mf][f][3] += f1.y;    \
                hacc[mf][f][0] = 0u;   hacc[mf][f][1] = 0u;      \
            }                                                    \
    } while (0)

    LOAD_A(0, a0); LOAD_B(0, bb0);
    #pragma unroll
    for (int ks = 0; ks < 32; ks += 2) {
        if (ks + 1 < 32) { LOAD_A(ks + 1, a1); LOAD_B(ks + 1, bb1); }
        DO_MMA(a0, bb0);
        if (ks + 2 < 32) { LOAD_A(ks + 2, a0); LOAD_B(ks + 2, bb0); }
        if (ks + 1 < 32) DO_MMA(a1, bb1);
        if ((ks & 2) == 2) PROMOTE();   // every 4 k16-slices
    }

    // ---------------- epilogue (register-resident gating) ----------------
    float xt[2][4][4], vv[2][4][4];
    #pragma unroll
    for (int mf = 0; mf < 2; mf++)
        #pragma unroll
        for (int f = 0; f < 4; f++)
            #pragma unroll
            for (int c = 0; c < 4; c++) {
                xt[mf][f][c] = fmaxf(acc[mf][f][c], 0.0f);
                vv[mf][f][c] = acc[mf][f + 4][c];
            }

    float av[ITq];
    #pragma unroll
    for (int i = 0; i < ITq; i++) av[i] = alphas[tok * ITq + i];

    float2 sc[4], gm[4], bt[4];
    #pragma unroll
    for (int f = 0; f < 4; f++) {
        const int col = wid * 32 + f * 8 + 2 * (lane & 3);
        sc[f] = *reinterpret_cast<const float2*>(scales + tok * Hq + col);
        gm[f] = *reinterpret_cast<const float2*>(gamma  + tok * Hq + col);
        bt[f] = *reinterpret_cast<const float2*>(beta   + tok * Hq + col);
    }

    constexpr float INVH = 1.0f / (float)Hq;
    const int q = lane >> 2;

    #pragma unroll
    for (int it = 0; it < ITq; it++) {
        float plo[2], phi[2];
        #pragma unroll
        for (int mf = 0; mf < 2; mf++) {
            plo[mf] = 0.0f; phi[mf] = 0.0f;
            #pragma unroll
            for (int f = 0; f < 4; f++) {
                plo[mf] += xt[mf][f][0] + xt[mf][f][1];
                phi[mf] += xt[mf][f][2] + xt[mf][f][3];
            }
        }
        #pragma unroll
        for (int off = 1; off <= 2; off <<= 1) {
            #pragma unroll
            for (int mf = 0; mf < 2; mf++) {
                plo[mf] += __shfl_xor_sync(0xffffffffu, plo[mf], off);
                phi[mf] += __shfl_xor_sync(0xffffffffu, phi[mf], off);
            }
        }
        const int buf = it & 1;
        if ((lane & 3) == 0) {
            red[buf][wid][q]      = plo[0];
            red[buf][wid][q + 8]  = phi[0];
            red[buf][wid][q + 16] = plo[1];
            red[buf][wid][q + 24] = phi[1];
        }
        __syncthreads();
        #pragma unroll
        for (int mf = 0; mf < 2; mf++) {
            const int rlo = mf * 16 + q;
            float slo = 0.0f, shi = 0.0f;
            #pragma unroll
            for (int w = 0; w < 8; w++) {
                slo += red[buf][w][rlo];
                shi += red[buf][w][rlo + 8];
            }
            const float dlo = av[it] * slo * INVH;
            const float dhi = av[it] * shi * INVH;
            #pragma unroll
            for (int f = 0; f < 4; f++) {
                xt[mf][f][0] = fmaxf(xt[mf][f][0] - dlo, 0.0f);
                xt[mf][f][1] = fmaxf(xt[mf][f][1] - dlo, 0.0f);
                xt[mf][f][2] = fmaxf(xt[mf][f][2] - dhi, 0.0f);
                xt[mf][f][3] = fmaxf(xt[mf][f][3] - dhi, 0.0f);
            }
        }
    }
    __syncthreads();

    float s[2][4][4];
    float sumlo[2] = {0, 0}, sumhi[2] = {0, 0};
    float sqlo[2]  = {0, 0}, sqhi[2]  = {0, 0};
    #pragma unroll
    for (int mf = 0; mf < 2; mf++)
        #pragma unroll
        for (int f = 0; f < 4; f++) {
            s[mf][f][0] = sc[f].x * xt[mf][f][0] * vv[mf][f][0];
            s[mf][f][1] = sc[f].y * xt[mf][f][1] * vv[mf][f][1];
            s[mf][f][2] = sc[f].x * xt[mf][f][2] * vv[mf][f][2];
            s[mf][f][3] = sc[f].y * xt[mf][f][3] * vv[mf][f][3];
            sumlo[mf] += s[mf][f][0] + s[mf][f][1];
            sumhi[mf] += s[mf][f][2] + s[mf][f][3];
            sqlo[mf]  += s[mf][f][0] * s[mf][f][0] + s[mf][f][1] * s[mf][f][1];
            sqhi[mf]  += s[mf][f][2] * s[mf][f][2] + s[mf][f][3] * s[mf][f][3];
        }
    #pragma unroll
    for (int off = 1; off <= 2; off <<= 1) {
        #pragma unroll
        for (int mf = 0; mf < 2; mf++) {
            sumlo[mf] += __shfl_xor_sync(0xffffffffu, sumlo[mf], off);
            sumhi[mf] += __shfl_xor_sync(0xffffffffu, sumhi[mf], off);
            sqlo[mf]  += __shfl_xor_sync(0xffffffffu, sqlo[mf],  off);
            sqhi[mf]  += __shfl_xor_sync(0xffffffffu, sqhi[mf],  off);
        }
    }
    if ((lane & 3) == 0) {
        red[0][wid][q]      = sumlo[0];
        red[0][wid][q + 8]  = sumhi[0];
        red[0][wid][q + 16] = sumlo[1];
        red[0][wid][q + 24] = sumhi[1];
        red[1][wid][q]      = sqlo[0];
        red[1][wid][q + 8]  = sqhi[0];
        red[1][wid][q + 16] = sqlo[1];
        red[1][wid][q + 24] = sqhi[1];
    }
    __syncthreads();

    #pragma unroll
    for (int mf = 0; mf < 2; mf++) {
        const int rlo = mf * 16 + q;
        float slo = 0, shi = 0, qlo = 0, qhi = 0;
        #pragma unroll
        for (int w = 0; w < 8; w++) {
            slo += red[0][w][rlo];   shi += red[0][w][rlo + 8];
            qlo += red[1][w][rlo];   qhi += red[1][w][rlo + 8];
        }
        const float mulo = slo * INVH;
        const float muhi = shi * INVH;
        const float ilo  = rsqrtf(fmaxf(qlo * INVH - mulo * mulo, 0.0f) + EPSq);
        const float ihi  = rsqrtf(fmaxf(qhi * INVH - muhi * muhi, 0.0f) + EPSq);

        const int row_lo = b0 + mf * 16 + q;
        float* olo = out + ((size_t)row_lo * Tq + tok) * Hq;
        float* ohi = olo + (size_t)8 * Tq * Hq;
        #pragma unroll
        for (int f = 0; f < 4; f++) {
            const int col = wid * 32 + f * 8 + 2 * (lane & 3);
            float2 v0, v1;
            v0.x = (s[mf][f][0] - mulo) * ilo * gm[f].x + bt[f].x;
            v0.y = (s[mf][f][1] - mulo) * ilo * gm[f].y + bt[f].y;
            v1.x = (s[mf][f][2] - muhi) * ihi * gm[f].x + bt[f].x;
            v1.y = (s[mf][f][3] - muhi) * ihi * gm[f].y + bt[f].y;
            *reinterpret_cast<float2*>(olo + col) = v0;
            *reinterpret_cast<float2*>(ohi + col) = v1;
        }
    }
}

// ---------------- host launch ----------------
extern "C" void kernel_launch(void* const* d_in, const int* in_sizes, int n_in,
                              void* d_out, int out_size) {
    const float* x      = (const float*)d_in[0];
    const float* w_in   = (const float*)d_in[1];
    const float* w_val  = (const float*)d_in[2];
    const float* alphas = (const float*)d_in[3];
    const float* scales = (const float*)d_in[4];
    const float* gamma  = (const float*)d_in[5];
    const float* beta   = (const float*)d_in[6];
    float* out = (float*)d_out;

    convert_kernel<<<1024 + 8192, 256>>>(x, w_in, w_val);

    dim3 grid(Bq / 32, Tq);
    gemm_fused_kernel<<<grid, 256>>>(alphas, scales, gamma, beta, out);
}

// round 13
// speedup vs baseline: 1.4407x; 1.4407x over previous
#include <cuda_runtime.h>
#include <cuda_fp16.h>
#include <cstdint>

// ---------------- problem constants ----------------
constexpr int Bq = 4096;
constexpr int Eq = 512;   // K
constexpr int Tq = 32;
constexpr int Hq = 256;
constexpr int ITq = 5;
#define EPSq 1e-6f

// ---------------- fragment-ready scratch ----------------
// A frags: [mtile32 128][ks 32][mfrag 2][lane 32][8 halves]       = 4 MB
// B frags: [tok 32][ks 32][warp 8][fpair 4][lane 32][8 halves]    = 16 MB
__device__ __align__(256) __half g_xa[(size_t)128 * 32 * 2 * 32 * 8];
__device__ __align__(256) __half g_xb[(size_t)32 * 32 * 8 * 4 * 32 * 8];

__device__ __forceinline__ void mma16816(float* d, const uint32_t* a,
                                         const uint32_t* b) {
    asm volatile(
        "mma.sync.aligned.m16n8k16.row.col.f32.f16.f16.f32 "
        "{%0,%1,%2,%3},{%4,%5,%6,%7},{%8,%9},{%0,%1,%2,%3};"
        : "+f"(d[0]), "+f"(d[1]), "+f"(d[2]), "+f"(d[3])
        : "r"(a[0]), "r"(a[1]), "r"(a[2]), "r"(a[3]), "r"(b[0]), "r"(b[1]));
}

// ---------------- kernel 1: fused conversions ----------------
__global__ __launch_bounds__(256)
void convert_kernel(const float* __restrict__ x,
                    const float* __restrict__ w_in,
                    const float* __restrict__ w_val) {
    __shared__ float tile[32][33];
    if (blockIdx.x < 1024) {
        const int idx   = blockIdx.x * 256 + threadIdx.x;
        const int lane  = idx & 31;
        const int mfrag = (idx >> 5) & 1;
        const int ks    = (idx >> 6) & 31;
        const int mtile = idx >> 11;
        const int r0 = mtile * 32 + mfrag * 16 + (lane >> 2);
        const int c0 = ks * 16 + 2 * (lane & 3);
        const float* xr0 = x + (size_t)r0 * Eq;
        const float* xr1 = xr0 + 8 * Eq;
        __half h[8];
        h[0] = __float2half_rn(xr0[c0]);     h[1] = __float2half_rn(xr0[c0 + 1]);
        h[2] = __float2half_rn(xr1[c0]);     h[3] = __float2half_rn(xr1[c0 + 1]);
        h[4] = __float2half_rn(xr0[c0 + 8]); h[5] = __float2half_rn(xr0[c0 + 9]);
        h[6] = __float2half_rn(xr1[c0 + 8]); h[7] = __float2half_rn(xr1[c0 + 9]);
        reinterpret_cast<uint4*>(g_xa)[idx] = *reinterpret_cast<uint4*>(h);
        return;
    }
    const int bz = blockIdx.x - 1024;       // 0..8191
    const int e0 = (bz & 15) * 32;
    const int h0 = ((bz >> 4) & 7) * 32;
    const int z  = bz >> 7;
    const int m  = z >> 5;
    const int t  = z & 31;
    const float* src = (m ? w_val : w_in) + (size_t)t * Eq * Hq;
    const int tx = threadIdx.x & 31;
    const int ty = threadIdx.x >> 5;
    #pragma unroll
    for (int r = ty; r < 32; r += 8)
        tile[r][tx] = src[(size_t)(e0 + r) * Hq + h0 + tx];
    __syncthreads();
    const int lane = threadIdx.x & 31;
    const int f    = (threadIdx.x >> 5) & 3;
    const int ksl  = threadIdx.x >> 7;            // 0/1
    const int ks   = (e0 >> 4) + ksl;
    const int k0   = ksl * 16 + 2 * (lane & 3);
    const int hc   = f * 8 + (lane >> 2);
    const int wp   = h0 >> 5;
    const int fi   = f + m * 4;                   // 0..7
    __half hv[4];
    hv[0] = __float2half_rn(tile[k0][hc]);
    hv[1] = __float2half_rn(tile[k0 + 1][hc]);
    hv[2] = __float2half_rn(tile[k0 + 8][hc]);
    hv[3] = __float2half_rn(tile[k0 + 9][hc]);
    const size_t di = (((((size_t)t * 32 + ks) * 8 + wp) * 4 + (fi >> 1)) * 32
                      + lane) * 2 + (fi & 1);
    reinterpret_cast<uint2*>(g_xb)[di] = *reinterpret_cast<uint2*>(hv);
}

// ---------------- kernel 2: all-LDG GEMM, deep-B pipeline + epilogue -------
__global__ __launch_bounds__(256, 2)
void gemm_fused_kernel(const float* __restrict__ alphas,
                       const float* __restrict__ scales,
                       const float* __restrict__ gamma,
                       const float* __restrict__ beta,
                       float* __restrict__ out)
{
    __shared__ float red[2][8][32];

    const int tid  = threadIdx.x;
    const int wid  = tid >> 5;
    const int lane = tid & 31;
    const int mtile = blockIdx.x;   // 0..127
    const int tok   = blockIdx.y;   // 0..31
    const int b0    = mtile * 32;

    const uint4* pa = reinterpret_cast<const uint4*>(g_xa)
                    + ((size_t)mtile * 32) * 2 * 32 + lane;
    const uint4* pb = reinterpret_cast<const uint4*>(g_xb)
                    + (((size_t)tok * 32) * 8 + wid) * 4 * 32 + lane;

    float acc[2][8][4];
    #pragma unroll
    for (int i = 0; i < 2; i++)
        #pragma unroll
        for (int j = 0; j < 8; j++)
            #pragma unroll
            for (int k = 0; k < 4; k++) acc[i][j][k] = 0.0f;

    uint4 a[2];
    uint4 bb[3][4];     // 3-stage B ring

    #define LOAD_A(ks, A) do {                                   \
        A[0] = pa[(size_t)(ks) * 64];                            \
        A[1] = pa[(size_t)(ks) * 64 + 32];                       \
    } while (0)
    #define LOAD_B(ks, BB) do {                                  \
        _Pragma("unroll")                                        \
        for (int j = 0; j < 4; j++)                              \
            BB[j] = pb[(size_t)(ks) * 1024 + j * 32];            \
    } while (0)
    #define DO_MMA(A, BB) do {                                   \
        _Pragma("unroll")                                        \
        for (int mf = 0; mf < 2; mf++)                           \
            _Pragma("unroll")                                    \
            for (int f = 0; f < 8; f++)                          \
                mma16816(acc[mf][f],                             \
                         reinterpret_cast<const uint32_t*>(&A[mf]), \
                         reinterpret_cast<const uint32_t*>(&BB[f >> 1]) + (f & 1) * 2); \
    } while (0)

    LOAD_B(0, bb[0]);
    LOAD_B(1, bb[1]);
    #pragma unroll
    for (int ks = 0; ks < 32; ks++) {
        if (ks + 2 < 32) LOAD_B(ks + 2, bb[(ks + 2) % 3]);
        LOAD_A(ks, a);
        DO_MMA(a, bb[ks % 3]);
    }

    // ---------------- epilogue (register-resident gating) ----------------
    float xt[2][4][4], vv[2][4][4];
    #pragma unroll
    for (int mf = 0; mf < 2; mf++)
        #pragma unroll
        for (int f = 0; f < 4; f++)
            #pragma unroll
            for (int c = 0; c < 4; c++) {
                xt[mf][f][c] = fmaxf(acc[mf][f][c], 0.0f);
                vv[mf][f][c] = acc[mf][f + 4][c];
            }

    float av[ITq];
    #pragma unroll
    for (int i = 0; i < ITq; i++) av[i] = alphas[tok * ITq + i];

    float2 sc[4], gm[4], bt[4];
    #pragma unroll
    for (int f = 0; f < 4; f++) {
        const int col = wid * 32 + f * 8 + 2 * (lane & 3);
        sc[f] = *reinterpret_cast<const float2*>(scales + tok * Hq + col);
        gm[f] = *reinterpret_cast<const float2*>(gamma  + tok * Hq + col);
        bt[f] = *reinterpret_cast<const float2*>(beta   + tok * Hq + col);
    }

    constexpr float INVH = 1.0f / (float)Hq;
    const int q = lane >> 2;

    #pragma unroll
    for (int it = 0; it < ITq; it++) {
        float plo[2], phi[2];
        #pragma unroll
        for (int mf = 0; mf < 2; mf++) {
            plo[mf] = 0.0f; phi[mf] = 0.0f;
            #pragma unroll
            for (int f = 0; f < 4; f++) {
                plo[mf] += xt[mf][f][0] + xt[mf][f][1];
                phi[mf] += xt[mf][f][2] + xt[mf][f][3];
            }
        }
        #pragma unroll
        for (int off = 1; off <= 2; off <<= 1) {
            #pragma unroll
            for (int mf = 0; mf < 2; mf++) {
                plo[mf] += __shfl_xor_sync(0xffffffffu, plo[mf], off);
                phi[mf] += __shfl_xor_sync(0xffffffffu, phi[mf], off);
            }
        }
        const int buf = it & 1;
        if ((lane & 3) == 0) {
            red[buf][wid][q]      = plo[0];
            red[buf][wid][q + 8]  = phi[0];
            red[buf][wid][q + 16] = plo[1];
            red[buf][wid][q + 24] = phi[1];
        }
        __syncthreads();
        #pragma unroll
        for (int mf = 0; mf < 2; mf++) {
            const int rlo = mf * 16 + q;
            float slo = 0.0f, shi = 0.0f;
            #pragma unroll
            for (int w = 0; w < 8; w++) {
                slo += red[buf][w][rlo];
                shi += red[buf][w][rlo + 8];
            }
            const float dlo = av[it] * slo * INVH;
            const float dhi = av[it] * shi * INVH;
            #pragma unroll
            for (int f = 0; f < 4; f++) {
                xt[mf][f][0] = fmaxf(xt[mf][f][0] - dlo, 0.0f);
                xt[mf][f][1] = fmaxf(xt[mf][f][1] - dlo, 0.0f);
                xt[mf][f][2] = fmaxf(xt[mf][f][2] - dhi, 0.0f);
                xt[mf][f][3] = fmaxf(xt[mf][f][3] - dhi, 0.0f);
            }
        }
    }
    __syncthreads();

    float s[2][4][4];
    float sumlo[2] = {0, 0}, sumhi[2] = {0, 0};
    float sqlo[2]  = {0, 0}, sqhi[2]  = {0, 0};
    #pragma unroll
    for (int mf = 0; mf < 2; mf++)
        #pragma unroll
        for (int f = 0; f < 4; f++) {
            s[mf][f][0] = sc[f].x * xt[mf][f][0] * vv[mf][f][0];
            s[mf][f][1] = sc[f].y * xt[mf][f][1] * vv[mf][f][1];
            s[mf][f][2] = sc[f].x * xt[mf][f][2] * vv[mf][f][2];
            s[mf][f][3] = sc[f].y * xt[mf][f][3] * vv[mf][f][3];
            sumlo[mf] += s[mf][f][0] + s[mf][f][1];
            sumhi[mf] += s[mf][f][2] + s[mf][f][3];
            sqlo[mf]  += s[mf][f][0] * s[mf][f][0] + s[mf][f][1] * s[mf][f][1];
            sqhi[mf]  += s[mf][f][2] * s[mf][f][2] + s[mf][f][3] * s[mf][f][3];
        }
    #pragma unroll
    for (int off = 1; off <= 2; off <<= 1) {
        #pragma unroll
        for (int mf = 0; mf < 2; mf++) {
            sumlo[mf] += __shfl_xor_sync(0xffffffffu, sumlo[mf], off);
            sumhi[mf] += __shfl_xor_sync(0xffffffffu, sumhi[mf], off);
            sqlo[mf]  += __shfl_xor_sync(0xffffffffu, sqlo[mf],  off);
            sqhi[mf]  += __shfl_xor_sync(0xffffffffu, sqhi[mf],  off);
        }
    }
    if ((lane & 3) == 0) {
        red[0][wid][q]      = sumlo[0];
        red[0][wid][q + 8]  = sumhi[0];
        red[0][wid][q + 16] = sumlo[1];
        red[0][wid][q + 24] = sumhi[1];
        red[1][wid][q]      = sqlo[0];
        red[1][wid][q + 8]  = sqhi[0];
        red[1][wid][q + 16] = sqlo[1];
        red[1][wid][q + 24] = sqhi[1];
    }
    __syncthreads();

    #pragma unroll
    for (int mf = 0; mf < 2; mf++) {
        const int rlo = mf * 16 + q;
        float slo = 0, shi = 0, qlo = 0, qhi = 0;
        #pragma unroll
        for (int w = 0; w < 8; w++) {
            slo += red[0][w][rlo];   shi += red[0][w][rlo + 8];
            qlo += red[1][w][rlo];   qhi += red[1][w][rlo + 8];
        }
        const float mulo = slo * INVH;
        const float muhi = shi * INVH;
        const float ilo  = rsqrtf(fmaxf(qlo * INVH - mulo * mulo, 0.0f) + EPSq);
        const float ihi  = rsqrtf(fmaxf(qhi * INVH - muhi * muhi, 0.0f) + EPSq);

        const int row_lo = b0 + mf * 16 + q;
        float* olo = out + ((size_t)row_lo * Tq + tok) * Hq;
        float* ohi = olo + (size_t)8 * Tq * Hq;
        #pragma unroll
        for (int f = 0; f < 4; f++) {
            const int col = wid * 32 + f * 8 + 2 * (lane & 3);
            float2 v0, v1;
            v0.x = (s[mf][f][0] - mulo) * ilo * gm[f].x + bt[f].x;
            v0.y = (s[mf][f][1] - mulo) * ilo * gm[f].y + bt[f].y;
            v1.x = (s[mf][f][2] - muhi) * ihi * gm[f].x + bt[f].x;
            v1.y = (s[mf][f][3] - muhi) * ihi * gm[f].y + bt[f].y;
            *reinterpret_cast<float2*>(olo + col) = v0;
            *reinterpret_cast<float2*>(ohi + col) = v1;
        }
    }
}

// ---------------- host launch ----------------
extern "C" void kernel_launch(void* const* d_in, const int* in_sizes, int n_in,
                              void* d_out, int out_size) {
    const float* x      = (const float*)d_in[0];
    const float* w_in   = (const float*)d_in[1];
    const float* w_val  = (const float*)d_in[2];
    const float* alphas = (const float*)d_in[3];
    const float* scales = (const float*)d_in[4];
    const float* gamma  = (const float*)d_in[5];
    const float* beta   = (const float*)d_in[6];
    float* out = (float*)d_out;

    convert_kernel<<<1024 + 8192, 256>>>(x, w_in, w_val);

    dim3 grid(Bq / 32, Tq);
    gemm_fused_kernel<<<grid, 256>>>(alphas, scales, gamma, beta, out);
}

// round 14
// speedup vs baseline: 1.4543x; 1.0095x over previous
#include <cuda_runtime.h>
#include <cuda_fp16.h>
#include <cstdint>

// ---------------- problem constants ----------------
constexpr int Bq = 4096;
constexpr int Eq = 512;   // K
constexpr int Tq = 32;
constexpr int Hq = 256;
constexpr int ITq = 5;
#define EPSq 1e-6f

constexpr int EPIT = 514;                    // epilogue pitch (floats)
constexpr int SMEM_BYTES = 32 * EPIT * 4;    // 65792 B per CTA

// ---------------- fragment-ready scratch ----------------
// A frags: [mtile32 128][ks 32][mfrag 2][lane 32][8 halves]       = 4 MB
// B frags: [tok 32][ks 32][warp 8][fpair 4][lane 32][8 halves]    = 16 MB
__device__ __align__(256) __half g_xa[(size_t)128 * 32 * 2 * 32 * 8];
__device__ __align__(256) __half g_xb[(size_t)32 * 32 * 8 * 4 * 32 * 8];

__device__ __forceinline__ void mma16816(float* d, const uint32_t* a,
                                         const uint32_t* b) {
    asm volatile(
        "mma.sync.aligned.m16n8k16.row.col.f32.f16.f16.f32 "
        "{%0,%1,%2,%3},{%4,%5,%6,%7},{%8,%9},{%0,%1,%2,%3};"
        : "+f"(d[0]), "+f"(d[1]), "+f"(d[2]), "+f"(d[3])
        : "r"(a[0]), "r"(a[1]), "r"(a[2]), "r"(a[3]), "r"(b[0]), "r"(b[1]));
}

// ---------------- kernel 1: fused conversions ----------------
__global__ __launch_bounds__(256)
void convert_kernel(const float* __restrict__ x,
                    const float* __restrict__ w_in,
                    const float* __restrict__ w_val) {
    __shared__ float tile[32][33];
    if (blockIdx.x < 1024) {
        const int idx   = blockIdx.x * 256 + threadIdx.x;
        const int lane  = idx & 31;
        const int mfrag = (idx >> 5) & 1;
        const int ks    = (idx >> 6) & 31;
        const int mtile = idx >> 11;
        const int r0 = mtile * 32 + mfrag * 16 + (lane >> 2);
        const int c0 = ks * 16 + 2 * (lane & 3);
        const float* xr0 = x + (size_t)r0 * Eq;
        const float* xr1 = xr0 + 8 * Eq;
        __half h[8];
        h[0] = __float2half_rn(xr0[c0]);     h[1] = __float2half_rn(xr0[c0 + 1]);
        h[2] = __float2half_rn(xr1[c0]);     h[3] = __float2half_rn(xr1[c0 + 1]);
        h[4] = __float2half_rn(xr0[c0 + 8]); h[5] = __float2half_rn(xr0[c0 + 9]);
        h[6] = __float2half_rn(xr1[c0 + 8]); h[7] = __float2half_rn(xr1[c0 + 9]);
        reinterpret_cast<uint4*>(g_xa)[idx] = *reinterpret_cast<uint4*>(h);
        return;
    }
    const int bz = blockIdx.x - 1024;       // 0..8191
    const int e0 = (bz & 15) * 32;
    const int h0 = ((bz >> 4) & 7) * 32;
    const int z  = bz >> 7;
    const int m  = z >> 5;
    const int t  = z & 31;
    const float* src = (m ? w_val : w_in) + (size_t)t * Eq * Hq;
    const int tx = threadIdx.x & 31;
    const int ty = threadIdx.x >> 5;
    #pragma unroll
    for (int r = ty; r < 32; r += 8)
        tile[r][tx] = src[(size_t)(e0 + r) * Hq + h0 + tx];
    __syncthreads();
    const int lane = threadIdx.x & 31;
    const int f    = (threadIdx.x >> 5) & 3;
    const int ksl  = threadIdx.x >> 7;            // 0/1
    const int ks   = (e0 >> 4) + ksl;
    const int k0   = ksl * 16 + 2 * (lane & 3);
    const int hc   = f * 8 + (lane >> 2);
    const int wp   = h0 >> 5;
    const int fi   = f + m * 4;                   // 0..7
    __half hv[4];
    hv[0] = __float2half_rn(tile[k0][hc]);
    hv[1] = __float2half_rn(tile[k0 + 1][hc]);
    hv[2] = __float2half_rn(tile[k0 + 8][hc]);
    hv[3] = __float2half_rn(tile[k0 + 9][hc]);
    const size_t di = (((((size_t)t * 32 + ks) * 8 + wp) * 4 + (fi >> 1)) * 32
                      + lane) * 2 + (fi & 1);
    reinterpret_cast<uint2*>(g_xb)[di] = *reinterpret_cast<uint2*>(hv);
}

// ---------------- kernel 2: all-LDG GEMM + single-barrier epilogue --------
__global__ __launch_bounds__(256, 2)
void gemm_fused_kernel(const float* __restrict__ alphas,
                       const float* __restrict__ scales,
                       const float* __restrict__ gamma,
                       const float* __restrict__ beta,
                       float* __restrict__ out)
{
    extern __shared__ float es[];   // [32 rows][EPIT]

    const int tid  = threadIdx.x;
    const int wid  = tid >> 5;
    const int lane = tid & 31;
    const int mtile = blockIdx.x;   // 0..127
    const int tok   = blockIdx.y;   // 0..31
    const int b0    = mtile * 32;

    const uint4* pa = reinterpret_cast<const uint4*>(g_xa)
                    + ((size_t)mtile * 32) * 2 * 32 + lane;
    const uint4* pb = reinterpret_cast<const uint4*>(g_xb)
                    + (((size_t)tok * 32) * 8 + wid) * 4 * 32 + lane;

    float acc[2][8][4];
    #pragma unroll
    for (int i = 0; i < 2; i++)
        #pragma unroll
        for (int j = 0; j < 8; j++)
            #pragma unroll
            for (int k = 0; k < 4; k++) acc[i][j][k] = 0.0f;

    uint4 a0[2], a1[2];
    uint4 bb0[4], bb1[4];

    #define LOAD_A(ks, A) do {                                   \
        A[0] = pa[(size_t)(ks) * 64];                            \
        A[1] = pa[(size_t)(ks) * 64 + 32];                       \
    } while (0)
    #define LOAD_B(ks, BB) do {                                  \
        _Pragma("unroll")                                        \
        for (int j = 0; j < 4; j++)                              \
            BB[j] = pb[(size_t)(ks) * 1024 + j * 32];            \
    } while (0)
    #define DO_MMA(A, BB) do {                                   \
        _Pragma("unroll")                                        \
        for (int mf = 0; mf < 2; mf++)                           \
            _Pragma("unroll")                                    \
            for (int f = 0; f < 8; f++)                          \
                mma16816(acc[mf][f],                             \
                         reinterpret_cast<const uint32_t*>(&A[mf]), \
                         reinterpret_cast<const uint32_t*>(&BB[f >> 1]) + (f & 1) * 2); \
    } while (0)

    LOAD_A(0, a0); LOAD_B(0, bb0);
    #pragma unroll
    for (int ks = 0; ks < 32; ks += 2) {
        if (ks + 1 < 32) { LOAD_A(ks + 1, a1); LOAD_B(ks + 1, bb1); }
        DO_MMA(a0, bb0);
        if (ks + 2 < 32) { LOAD_A(ks + 2, a0); LOAD_B(ks + 2, bb0); }
        if (ks + 1 < 32) DO_MMA(a1, bb1);
    }

    // ---------------- epilogue: one smem transpose, then warp-local rows ----
    // scatter accumulators: es[row][col], col = wid*32 + f*8 + 2*(lane&3)
    #pragma unroll
    for (int mf = 0; mf < 2; mf++)
        #pragma unroll
        for (int f = 0; f < 8; f++) {
            const int row = mf * 16 + (lane >> 2);
            const int col = wid * 32 + ((f & 3) * 8) + 2 * (lane & 3)
                          + (f >> 2) * 256;
            *reinterpret_cast<float2*>(&es[row * EPIT + col]) =
                make_float2(acc[mf][f][0], acc[mf][f][1]);
            *reinterpret_cast<float2*>(&es[(row + 8) * EPIT + col]) =
                make_float2(acc[mf][f][2], acc[mf][f][3]);
        }
    __syncthreads();

    // warp w owns rows 4w..4w+3 (full 256-col rows, lane-strided by 32)
    float av[ITq];
    #pragma unroll
    for (int i = 0; i < ITq; i++) av[i] = alphas[tok * ITq + i];

    float sc[8], gm[8], bt[8];
    #pragma unroll
    for (int j = 0; j < 8; j++) {
        sc[j] = scales[tok * Hq + 32 * j + lane];
        gm[j] = gamma [tok * Hq + 32 * j + lane];
        bt[j] = beta  [tok * Hq + 32 * j + lane];
    }

    constexpr float INVH = 1.0f / (float)Hq;
    #pragma unroll
    for (int rr = 0; rr < 4; rr++) {
        const int lrow = wid * 4 + rr;
        float xt[8], xv[8];
        #pragma unroll
        for (int j = 0; j < 8; j++) {
            xt[j] = fmaxf(es[lrow * EPIT + 32 * j + lane], 0.0f);
            xv[j] = es[lrow * EPIT + 256 + 32 * j + lane];
        }
        #pragma unroll
        for (int it = 0; it < ITq; it++) {
            float s = 0.0f;
            #pragma unroll
            for (int j = 0; j < 8; j++) s += xt[j];
            #pragma unroll
            for (int off = 16; off > 0; off >>= 1)
                s += __shfl_xor_sync(0xffffffffu, s, off);
            const float d = av[it] * s * INVH;
            #pragma unroll
            for (int j = 0; j < 8; j++) xt[j] = fmaxf(xt[j] - d, 0.0f);
        }
        float sv[8], sum = 0.0f, sq = 0.0f;
        #pragma unroll
        for (int j = 0; j < 8; j++) {
            sv[j] = sc[j] * xt[j] * xv[j];
            sum += sv[j];
            sq  += sv[j] * sv[j];
        }
        #pragma unroll
        for (int off = 16; off > 0; off >>= 1) {
            sum += __shfl_xor_sync(0xffffffffu, sum, off);
            sq  += __shfl_xor_sync(0xffffffffu, sq,  off);
        }
        const float mu  = sum * INVH;
        const float var = fmaxf(sq * INVH - mu * mu, 0.0f);
        const float inv = rsqrtf(var + EPSq);
        float* op = out + ((size_t)(b0 + lrow) * Tq + tok) * Hq;
        #pragma unroll
        for (int j = 0; j < 8; j++)
            op[32 * j + lane] = (sv[j] - mu) * inv * gm[j] + bt[j];
    }
}

// ---------------- host launch ----------------
extern "C" void kernel_launch(void* const* d_in, const int* in_sizes, int n_in,
                              void* d_out, int out_size) {
    const float* x      = (const float*)d_in[0];
    const float* w_in   = (const float*)d_in[1];
    const float* w_val  = (const float*)d_in[2];
    const float* alphas = (const float*)d_in[3];
    const float* scales = (const float*)d_in[4];
    const float* gamma  = (const float*)d_in[5];
    const float* beta   = (const float*)d_in[6];
    float* out = (float*)d_out;

    convert_kernel<<<1024 + 8192, 256>>>(x, w_in, w_val);

    cudaFuncSetAttribute(gemm_fused_kernel,
                         cudaFuncAttributeMaxDynamicSharedMemorySize, SMEM_BYTES);
    dim3 grid(Bq / 32, Tq);
    gemm_fused_kernel<<<grid, 256, SMEM_BYTES>>>(alphas, scales, gamma, beta, out);
}

// round 15
// speedup vs baseline: 1.4660x; 1.0080x over previous
#include <cuda_runtime.h>
#include <cuda_fp16.h>
#include <cstdint>

// ---------------- problem constants ----------------
constexpr int Bq = 4096;
constexpr int Eq = 512;   // K
constexpr int Tq = 32;
constexpr int Hq = 256;
constexpr int ITq = 5;
#define EPSq 1e-6f

constexpr int EPIT = 514;                    // epilogue pitch (floats)
constexpr int SMEM_BYTES = 32 * EPIT * 4;    // 65792 B per CTA

// ---------------- fragment-ready scratch ----------------
// A frags: [mtile32 128][ks 32][mfrag 2][lane 32][8 halves]       = 4 MB
// B frags: [tok 32][ks 32][warp 8][fpair 4][lane 32][8 halves]    = 16 MB
__device__ __align__(256) __half g_xa[(size_t)128 * 32 * 2 * 32 * 8];
__device__ __align__(256) __half g_xb[(size_t)32 * 32 * 8 * 4 * 32 * 8];

__device__ __forceinline__ void mma16816(float* d, const uint32_t* a,
                                         const uint32_t* b) {
    asm volatile(
        "mma.sync.aligned.m16n8k16.row.col.f32.f16.f16.f32 "
        "{%0,%1,%2,%3},{%4,%5,%6,%7},{%8,%9},{%0,%1,%2,%3};"
        : "+f"(d[0]), "+f"(d[1]), "+f"(d[2]), "+f"(d[3])
        : "r"(a[0]), "r"(a[1]), "r"(a[2]), "r"(a[3]), "r"(b[0]), "r"(b[1]));
}

// ---------------- kernel 1: fused conversions (optimized) ----------------
// blocks [0,1024):     x -> A fragments (float2 loads)
// blocks [1024,5120):  w -> B fragments (64x32 tile per block)
__global__ __launch_bounds__(256)
void convert_kernel(const float* __restrict__ x,
                    const float* __restrict__ w_in,
                    const float* __restrict__ w_val) {
    __shared__ float tile[64][33];
    if (blockIdx.x < 1024) {
        const int idx   = blockIdx.x * 256 + threadIdx.x;
        const int lane  = idx & 31;
        const int mfrag = (idx >> 5) & 1;
        const int ks    = (idx >> 6) & 31;
        const int mtile = idx >> 11;
        const int r0 = mtile * 32 + mfrag * 16 + (lane >> 2);
        const int c0 = ks * 16 + 2 * (lane & 3);
        const float2* p0 = reinterpret_cast<const float2*>(x + (size_t)r0 * Eq + c0);
        const float2* p1 = reinterpret_cast<const float2*>(x + (size_t)(r0 + 8) * Eq + c0);
        float2 v00 = p0[0], v01 = p0[4];   // (c0,c0+1), (c0+8,c0+9)
        float2 v10 = p1[0], v11 = p1[4];
        __half h[8];
        h[0] = __float2half_rn(v00.x); h[1] = __float2half_rn(v00.y);
        h[2] = __float2half_rn(v10.x); h[3] = __float2half_rn(v10.y);
        h[4] = __float2half_rn(v01.x); h[5] = __float2half_rn(v01.y);
        h[6] = __float2half_rn(v11.x); h[7] = __float2half_rn(v11.y);
        reinterpret_cast<uint4*>(g_xa)[idx] = *reinterpret_cast<uint4*>(h);
        return;
    }
    // w path: 4096 blocks, each handles a 64(e) x 32(h) tile
    const int bz = blockIdx.x - 1024;       // 0..4095
    const int e0 = (bz & 7) * 64;           // 8 e-tiles of 64
    const int h0 = ((bz >> 3) & 7) * 32;    // 8 h-tiles of 32
    const int z  = bz >> 6;                 // 0..63
    const int m  = z >> 5;                  // 0: w_in, 1: w_val
    const int t  = z & 31;
    const float* src = (m ? w_val : w_in) + (size_t)t * Eq * Hq;
    const int tx = threadIdx.x & 31;
    const int ty = threadIdx.x >> 5;
    #pragma unroll
    for (int r = ty; r < 64; r += 8)
        tile[r][tx] = src[(size_t)(e0 + r) * Hq + h0 + tx];
    __syncthreads();
    const int lane = threadIdx.x & 31;
    const int f    = (threadIdx.x >> 5) & 3;
    const int ksl  = threadIdx.x >> 7;            // 0/1
    const int hc   = f * 8 + (lane >> 2);
    const int wp   = h0 >> 5;
    const int fi   = f + m * 4;                   // 0..7
    #pragma unroll
    for (int eh = 0; eh < 2; eh++) {
        const int ks = (e0 >> 4) + eh * 2 + ksl;
        const int k0 = eh * 32 + ksl * 16 + 2 * (lane & 3);
        __half hv[4];
        hv[0] = __float2half_rn(tile[k0][hc]);
        hv[1] = __float2half_rn(tile[k0 + 1][hc]);
        hv[2] = __float2half_rn(tile[k0 + 8][hc]);
        hv[3] = __float2half_rn(tile[k0 + 9][hc]);
        const size_t di = (((((size_t)t * 32 + ks) * 8 + wp) * 4 + (fi >> 1)) * 32
                          + lane) * 2 + (fi & 1);
        reinterpret_cast<uint2*>(g_xb)[di] = *reinterpret_cast<uint2*>(hv);
    }
}

// ---------------- kernel 2: all-LDG GEMM + single-barrier epilogue --------
__global__ __launch_bounds__(256, 2)
void gemm_fused_kernel(const float* __restrict__ alphas,
                       const float* __restrict__ scales,
                       const float* __restrict__ gamma,
                       const float* __restrict__ beta,
                       float* __restrict__ out)
{
    extern __shared__ float es[];   // [32 rows][EPIT]

    const int tid  = threadIdx.x;
    const int wid  = tid >> 5;
    const int lane = tid & 31;
    const int mtile = blockIdx.x;   // 0..127
    const int tok   = blockIdx.y;   // 0..31
    const int b0    = mtile * 32;

    const uint4* pa = reinterpret_cast<const uint4*>(g_xa)
                    + ((size_t)mtile * 32) * 2 * 32 + lane;
    const uint4* pb = reinterpret_cast<const uint4*>(g_xb)
                    + (((size_t)tok * 32) * 8 + wid) * 4 * 32 + lane;

    float acc[2][8][4];
    #pragma unroll
    for (int i = 0; i < 2; i++)
        #pragma unroll
        for (int j = 0; j < 8; j++)
            #pragma unroll
            for (int k = 0; k < 4; k++) acc[i][j][k] = 0.0f;

    uint4 a0[2], a1[2];
    uint4 bb0[4], bb1[4];

    #define LOAD_A(ks, A) do {                                   \
        A[0] = pa[(size_t)(ks) * 64];                            \
        A[1] = pa[(size_t)(ks) * 64 + 32];                       \
    } while (0)
    #define LOAD_B(ks, BB) do {                                  \
        _Pragma("unroll")                                        \
        for (int j = 0; j < 4; j++)                              \
            BB[j] = pb[(size_t)(ks) * 1024 + j * 32];            \
    } while (0)
    #define DO_MMA(A, BB) do {                                   \
        _Pragma("unroll")                                        \
        for (int mf = 0; mf < 2; mf++)                           \
            _Pragma("unroll")                                    \
            for (int f = 0; f < 8; f++)                          \
                mma16816(acc[mf][f],                             \
                         reinterpret_cast<const uint32_t*>(&A[mf]), \
                         reinterpret_cast<const uint32_t*>(&BB[f >> 1]) + (f & 1) * 2); \
    } while (0)

    LOAD_A(0, a0); LOAD_B(0, bb0);
    #pragma unroll
    for (int ks = 0; ks < 32; ks += 2) {
        if (ks + 1 < 32) { LOAD_A(ks + 1, a1); LOAD_B(ks + 1, bb1); }
        DO_MMA(a0, bb0);
        if (ks + 2 < 32) { LOAD_A(ks + 2, a0); LOAD_B(ks + 2, bb0); }
        if (ks + 1 < 32) DO_MMA(a1, bb1);
    }

    // ---------------- epilogue: one smem transpose, then warp-local rows ----
    #pragma unroll
    for (int mf = 0; mf < 2; mf++)
        #pragma unroll
        for (int f = 0; f < 8; f++) {
            const int row = mf * 16 + (lane >> 2);
            const int col = wid * 32 + ((f & 3) * 8) + 2 * (lane & 3)
                          + (f >> 2) * 256;
            *reinterpret_cast<float2*>(&es[row * EPIT + col]) =
                make_float2(acc[mf][f][0], acc[mf][f][1]);
            *reinterpret_cast<float2*>(&es[(row + 8) * EPIT + col]) =
                make_float2(acc[mf][f][2], acc[mf][f][3]);
        }
    __syncthreads();

    float av[ITq];
    #pragma unroll
    for (int i = 0; i < ITq; i++) av[i] = alphas[tok * ITq + i];

    float sc[8], gm[8], bt[8];
    #pragma unroll
    for (int j = 0; j < 8; j++) {
        sc[j] = scales[tok * Hq + 32 * j + lane];
        gm[j] = gamma [tok * Hq + 32 * j + lane];
        bt[j] = beta  [tok * Hq + 32 * j + lane];
    }

    constexpr float INVH = 1.0f / (float)Hq;
    #pragma unroll
    for (int rr = 0; rr < 4; rr++) {
        const int lrow = wid * 4 + rr;
        float xt[8], xv[8];
        #pragma unroll
        for (int j = 0; j < 8; j++) {
            xt[j] = fmaxf(es[lrow * EPIT + 32 * j + lane], 0.0f);
            xv[j] = es[lrow * EPIT + 256 + 32 * j + lane];
        }
        #pragma unroll
        for (int it = 0; it < ITq; it++) {
            float s = 0.0f;
            #pragma unroll
            for (int j = 0; j < 8; j++) s += xt[j];
            #pragma unroll
            for (int off = 16; off > 0; off >>= 1)
                s += __shfl_xor_sync(0xffffffffu, s, off);
            const float d = av[it] * s * INVH;
            #pragma unroll
            for (int j = 0; j < 8; j++) xt[j] = fmaxf(xt[j] - d, 0.0f);
        }
        float sv[8], sum = 0.0f, sq = 0.0f;
        #pragma unroll
        for (int j = 0; j < 8; j++) {
            sv[j] = sc[j] * xt[j] * xv[j];
            sum += sv[j];
            sq  += sv[j] * sv[j];
        }
        #pragma unroll
        for (int off = 16; off > 0; off >>= 1) {
            sum += __shfl_xor_sync(0xffffffffu, sum, off);
            sq  += __shfl_xor_sync(0xffffffffu, sq,  off);
        }
        const float mu  = sum * INVH;
        const float var = fmaxf(sq * INVH - mu * mu, 0.0f);
        const float inv = rsqrtf(var + EPSq);
        float* op = out + ((size_t)(b0 + lrow) * Tq + tok) * Hq;
        #pragma unroll
        for (int j = 0; j < 8; j++)
            op[32 * j + lane] = (sv[j] - mu) * inv * gm[j] + bt[j];
    }
}

// ---------------- host launch ----------------
extern "C" void kernel_launch(void* const* d_in, const int* in_sizes, int n_in,
                              void* d_out, int out_size) {
    const float* x      = (const float*)d_in[0];
    const float* w_in   = (const float*)d_in[1];
    const float* w_val  = (const float*)d_in[2];
    const float* alphas = (const float*)d_in[3];
    const float* scales = (const float*)d_in[4];
    const float* gamma  = (const float*)d_in[5];
    const float* beta   = (const float*)d_in[6];
    float* out = (float*)d_out;

    convert_kernel<<<1024 + 4096, 256>>>(x, w_in, w_val);

    cudaFuncSetAttribute(gemm_fused_kernel,
                         cudaFuncAttributeMaxDynamicSharedMemorySize, SMEM_BYTES);
    dim3 grid(Bq / 32, Tq);
    gemm_fused_kernel<<<grid, 256, SMEM_BYTES>>>(alphas, scales, gamma, beta, out);
}

// round 16
// speedup vs baseline: 1.4705x; 1.0030x over previous
#include <cuda_runtime.h>
#include <cuda_fp16.h>
#include <cstdint>

// ---------------- problem constants ----------------
constexpr int Bq = 4096;
constexpr int Eq = 512;   // K
constexpr int Tq = 32;
constexpr int Hq = 256;
constexpr int ITq = 5;
#define EPSq 1e-6f

constexpr int EPIT = 514;                    // epilogue pitch (floats)
constexpr int SMEM_BYTES = 32 * EPIT * 4;    // 65792 B per CTA

// ---------------- fragment-ready scratch ----------------
// A frags: [mtile32 128][ks 32][mfrag 2][lane 32][8 halves]       = 4 MB
// B frags: [tok 32][ks 32][warp 8][fpair 4][lane 32][8 halves]    = 16 MB
__device__ __align__(256) __half g_xa[(size_t)128 * 32 * 2 * 32 * 8];
__device__ __align__(256) __half g_xb[(size_t)32 * 32 * 8 * 4 * 32 * 8];

__device__ __forceinline__ void mma16816(float* d, const uint32_t* a,
                                         const uint32_t* b) {
    asm volatile(
        "mma.sync.aligned.m16n8k16.row.col.f32.f16.f16.f32 "
        "{%0,%1,%2,%3},{%4,%5,%6,%7},{%8,%9},{%0,%1,%2,%3};"
        : "+f"(d[0]), "+f"(d[1]), "+f"(d[2]), "+f"(d[3])
        : "r"(a[0]), "r"(a[1]), "r"(a[2]), "r"(a[3]), "r"(b[0]), "r"(b[1]));
}

// non-coherent 16-byte load (read-only data path)
__device__ __forceinline__ uint4 ldg_nc16(const uint4* p) {
    uint4 v;
    asm volatile("ld.global.nc.v4.u32 {%0,%1,%2,%3}, [%4];"
                 : "=r"(v.x), "=r"(v.y), "=r"(v.z), "=r"(v.w) : "l"(p));
    return v;
}

// ---------------- kernel 1: fused conversions ----------------
// blocks [0,1024):     x -> A fragments (float2 loads)
// blocks [1024,5120):  w -> B fragments (64x32 tile per block)
__global__ __launch_bounds__(256)
void convert_kernel(const float* __restrict__ x,
                    const float* __restrict__ w_in,
                    const float* __restrict__ w_val) {
    __shared__ float tile[64][33];
    if (blockIdx.x < 1024) {
        const int idx   = blockIdx.x * 256 + threadIdx.x;
        const int lane  = idx & 31;
        const int mfrag = (idx >> 5) & 1;
        const int ks    = (idx >> 6) & 31;
        const int mtile = idx >> 11;
        const int r0 = mtile * 32 + mfrag * 16 + (lane >> 2);
        const int c0 = ks * 16 + 2 * (lane & 3);
        const float2* p0 = reinterpret_cast<const float2*>(x + (size_t)r0 * Eq + c0);
        const float2* p1 = reinterpret_cast<const float2*>(x + (size_t)(r0 + 8) * Eq + c0);
        float2 v00 = p0[0], v01 = p0[4];
        float2 v10 = p1[0], v11 = p1[4];
        __half h[8];
        h[0] = __float2half_rn(v00.x); h[1] = __float2half_rn(v00.y);
        h[2] = __float2half_rn(v10.x); h[3] = __float2half_rn(v10.y);
        h[4] = __float2half_rn(v01.x); h[5] = __float2half_rn(v01.y);
        h[6] = __float2half_rn(v11.x); h[7] = __float2half_rn(v11.y);
        reinterpret_cast<uint4*>(g_xa)[idx] = *reinterpret_cast<uint4*>(h);
        return;
    }
    const int bz = blockIdx.x - 1024;       // 0..4095
    const int e0 = (bz & 7) * 64;
    const int h0 = ((bz >> 3) & 7) * 32;
    const int z  = bz >> 6;
    const int m  = z >> 5;
    const int t  = z & 31;
    const float* src = (m ? w_val : w_in) + (size_t)t * Eq * Hq;
    const int tx = threadIdx.x & 31;
    const int ty = threadIdx.x >> 5;
    #pragma unroll
    for (int r = ty; r < 64; r += 8)
        tile[r][tx] = src[(size_t)(e0 + r) * Hq + h0 + tx];
    __syncthreads();
    const int lane = threadIdx.x & 31;
    const int f    = (threadIdx.x >> 5) & 3;
    const int ksl  = threadIdx.x >> 7;
    const int hc   = f * 8 + (lane >> 2);
    const int wp   = h0 >> 5;
    const int fi   = f + m * 4;
    #pragma unroll
    for (int eh = 0; eh < 2; eh++) {
        const int ks = (e0 >> 4) + eh * 2 + ksl;
        const int k0 = eh * 32 + ksl * 16 + 2 * (lane & 3);
        __half hv[4];
        hv[0] = __float2half_rn(tile[k0][hc]);
        hv[1] = __float2half_rn(tile[k0 + 1][hc]);
        hv[2] = __float2half_rn(tile[k0 + 8][hc]);
        hv[3] = __float2half_rn(tile[k0 + 9][hc]);
        const size_t di = (((((size_t)t * 32 + ks) * 8 + wp) * 4 + (fi >> 1)) * 32
                          + lane) * 2 + (fi & 1);
        reinterpret_cast<uint2*>(g_xb)[di] = *reinterpret_cast<uint2*>(hv);
    }
}

// ---------------- kernel 2: all-LDG(.nc) GEMM + single-barrier epilogue ----
__global__ __launch_bounds__(256, 2)
void gemm_fused_kernel(const float* __restrict__ alphas,
                       const float* __restrict__ scales,
                       const float* __restrict__ gamma,
                       const float* __restrict__ beta,
                       float* __restrict__ out)
{
    extern __shared__ float es[];   // [32 rows][EPIT]

    const int tid  = threadIdx.x;
    const int wid  = tid >> 5;
    const int lane = tid & 31;
    const int mtile = blockIdx.x;   // 0..127
    const int tok   = blockIdx.y;   // 0..31
    const int b0    = mtile * 32;

    const uint4* pa = reinterpret_cast<const uint4*>(g_xa)
                    + ((size_t)mtile * 32) * 2 * 32 + lane;
    const uint4* pb = reinterpret_cast<const uint4*>(g_xb)
                    + (((size_t)tok * 32) * 8 + wid) * 4 * 32 + lane;

    float acc[2][8][4];
    #pragma unroll
    for (int i = 0; i < 2; i++)
        #pragma unroll
        for (int j = 0; j < 8; j++)
            #pragma unroll
            for (int k = 0; k < 4; k++) acc[i][j][k] = 0.0f;

    uint4 a0[2], a1[2];
    uint4 bb0[4], bb1[4];

    #define LOAD_A(ks, A) do {                                   \
        A[0] = ldg_nc16(pa + (size_t)(ks) * 64);                 \
        A[1] = ldg_nc16(pa + (size_t)(ks) * 64 + 32);            \
    } while (0)
    #define LOAD_B(ks, BB) do {                                  \
        _Pragma("unroll")                                        \
        for (int j = 0; j < 4; j++)                              \
            BB[j] = ldg_nc16(pb + (size_t)(ks) * 1024 + j * 32); \
    } while (0)
    #define DO_MMA(A, BB) do {                                   \
        _Pragma("unroll")                                        \
        for (int mf = 0; mf < 2; mf++)                           \
            _Pragma("unroll")                                    \
            for (int f = 0; f < 8; f++)                          \
                mma16816(acc[mf][f],                             \
                         reinterpret_cast<const uint32_t*>(&A[mf]), \
                         reinterpret_cast<const uint32_t*>(&BB[f >> 1]) + (f & 1) * 2); \
    } while (0)

    LOAD_A(0, a0); LOAD_B(0, bb0);
    #pragma unroll
    for (int ks = 0; ks < 32; ks += 2) {
        if (ks + 1 < 32) { LOAD_A(ks + 1, a1); LOAD_B(ks + 1, bb1); }
        DO_MMA(a0, bb0);
        if (ks + 2 < 32) { LOAD_A(ks + 2, a0); LOAD_B(ks + 2, bb0); }
        if (ks + 1 < 32) DO_MMA(a1, bb1);
    }

    // ---------------- epilogue: one smem transpose, then warp-local rows ----
    #pragma unroll
    for (int mf = 0; mf < 2; mf++)
        #pragma unroll
        for (int f = 0; f < 8; f++) {
            const int row = mf * 16 + (lane >> 2);
            const int col = wid * 32 + ((f & 3) * 8) + 2 * (lane & 3)
                          + (f >> 2) * 256;
            *reinterpret_cast<float2*>(&es[row * EPIT + col]) =
                make_float2(acc[mf][f][0], acc[mf][f][1]);
            *reinterpret_cast<float2*>(&es[(row + 8) * EPIT + col]) =
                make_float2(acc[mf][f][2], acc[mf][f][3]);
        }
    __syncthreads();

    float av[ITq];
    #pragma unroll
    for (int i = 0; i < ITq; i++) av[i] = alphas[tok * ITq + i];

    float sc[8], gm[8], bt[8];
    #pragma unroll
    for (int j = 0; j < 8; j++) {
        sc[j] = scales[tok * Hq + 32 * j + lane];
        gm[j] = gamma [tok * Hq + 32 * j + lane];
        bt[j] = beta  [tok * Hq + 32 * j + lane];
    }

    constexpr float INVH = 1.0f / (float)Hq;
    #pragma unroll
    for (int rr = 0; rr < 4; rr++) {
        const int lrow = wid * 4 + rr;
        float xt[8], xv[8];
        #pragma unroll
        for (int j = 0; j < 8; j++) {
            xt[j] = fmaxf(es[lrow * EPIT + 32 * j + lane], 0.0f);
            xv[j] = es[lrow * EPIT + 256 + 32 * j + lane];
        }
        #pragma unroll
        for (int it = 0; it < ITq; it++) {
            float s = 0.0f;
            #pragma unroll
            for (int j = 0; j < 8; j++) s += xt[j];
            #pragma unroll
            for (int off = 16; off > 0; off >>= 1)
                s += __shfl_xor_sync(0xffffffffu, s, off);
            const float d = av[it] * s * INVH;
            #pragma unroll
            for (int j = 0; j < 8; j++) xt[j] = fmaxf(xt[j] - d, 0.0f);
        }
        float sv[8], sum = 0.0f, sq = 0.0f;
        #pragma unroll
        for (int j = 0; j < 8; j++) {
            sv[j] = sc[j] * xt[j] * xv[j];
            sum += sv[j];
            sq  += sv[j] * sv[j];
        }
        #pragma unroll
        for (int off = 16; off > 0; off >>= 1) {
            sum += __shfl_xor_sync(0xffffffffu, sum, off);
            sq  += __shfl_xor_sync(0xffffffffu, sq,  off);
        }
        const float mu  = sum * INVH;
        const float var = fmaxf(sq * INVH - mu * mu, 0.0f);
        const float inv = rsqrtf(var + EPSq);
        float* op = out + ((size_t)(b0 + lrow) * Tq + tok) * Hq;
        #pragma unroll
        for (int j = 0; j < 8; j++)
            op[32 * j + lane] = (sv[j] - mu) * inv * gm[j] + bt[j];
    }
}

// ---------------- host launch ----------------
extern "C" void kernel_launch(void* const* d_in, const int* in_sizes, int n_in,
                              void* d_out, int out_size) {
    const float* x      = (const float*)d_in[0];
    const float* w_in   = (const float*)d_in[1];
    const float* w_val  = (const float*)d_in[2];
    const float* alphas = (const float*)d_in[3];
    const float* scales = (const float*)d_in[4];
    const float* gamma  = (const float*)d_in[5];
    const float* beta   = (const float*)d_in[6];
    float* out = (float*)d_out;

    convert_kernel<<<1024 + 4096, 256>>>(x, w_in, w_val);

    cudaFuncSetAttribute(gemm_fused_kernel,
                         cudaFuncAttributeMaxDynamicSharedMemorySize, SMEM_BYTES);
    dim3 grid(Bq / 32, Tq);
    gemm_fused_kernel<<<grid, 256, SMEM_BYTES>>>(alphas, scales, gamma, beta, out);
}